// round 1
// baseline (speedup 1.0000x reference)
#include <cuda_runtime.h>

#define BATCH 4
#define CH    512
#define HW    4096
#define AD    512

#define BM  128
#define BN  128
#define BKK 16

// Scratch (allocation-free: __device__ globals)
__device__ float g_q[BATCH * HW * AD];            // [B][N][A]  (a contiguous)
__device__ float g_k[BATCH * HW * AD];            // [B][N][A]  == k^T
__device__ float g_v[BATCH * HW * CH];            // [B][N][C]
__device__ float g_S[(size_t)BATCH * HW * HW];    // [B][N][N]  scores, then P in place

// ---------------------------------------------------------------------------
// FMA-only exp (avoids MUFU bottleneck: 64M+ exps would cost ~0.5ms on MUFU).
// Valid for x <= 0 (all our uses). ~1e-7 relative error.
// ---------------------------------------------------------------------------
__device__ __forceinline__ float fast_exp_neg(float x) {
    float t = x * 1.4426950408889634f;     // log2(e)
    t = fmaxf(t, -126.0f);                 // clamp: underflow -> ~0
    float r = rintf(t);
    float f = t - r;                       // f in [-0.5, 0.5]
    float p = 1.3333558e-3f;
    p = fmaf(p, f, 9.6181291e-3f);
    p = fmaf(p, f, 5.5504110e-2f);
    p = fmaf(p, f, 2.4022651e-1f);
    p = fmaf(p, f, 6.9314718e-1f);
    p = fmaf(p, f, 1.0f);
    int i = (int)r;
    return __int_as_float(__float_as_int(p) + (i << 23));
}

// ---------------------------------------------------------------------------
// K1: fused projections. Y[n,a] = sum_c W[a,c] * X[c,n] + bias[a]
// grid.z = b*3 + p  (p: 0=q, 1=k, 2=v)
// ---------------------------------------------------------------------------
__global__ __launch_bounds__(256, 2) void k_proj(
    const float* __restrict__ x,
    const float* __restrict__ Wq, const float* __restrict__ bq,
    const float* __restrict__ Wk, const float* __restrict__ bk,
    const float* __restrict__ Wv, const float* __restrict__ bv)
{
    int z = blockIdx.z;
    int b = z / 3, p = z % 3;
    const float* W    = (p == 0) ? Wq : ((p == 1) ? Wk : Wv);
    const float* bias = (p == 0) ? bq : ((p == 1) ? bk : bv);
    float* Y = ((p == 0) ? g_q : ((p == 1) ? g_k : g_v)) + (size_t)b * HW * AD;
    const float* X = x + (size_t)b * CH * HW;

    int n0 = blockIdx.x * BM;
    int a0 = blockIdx.y * BN;

    __shared__ float As[BKK][BM + 4];
    __shared__ float Bs[BKK][BN + 4];

    int tid = threadIdx.x;
    int tx = tid & 15, ty = tid >> 4;
    int r8 = tid >> 5, c4 = tid & 31;   // direct-load mapping
    int lr = tid >> 2, lq = tid & 3;    // transpose-load mapping

    float acc[8][8];
    #pragma unroll
    for (int i = 0; i < 8; i++)
        #pragma unroll
        for (int j = 0; j < 8; j++) acc[i][j] = 0.f;

    for (int c0 = 0; c0 < CH; c0 += BKK) {
        // As[kk][mm] = X[(c0+kk)*HW + n0+mm]   (n contiguous -> direct float4)
        #pragma unroll
        for (int s = 0; s < 2; s++) {
            int kr = r8 + s * 8;
            float4 t = *reinterpret_cast<const float4*>(&X[(size_t)(c0 + kr) * HW + n0 + c4 * 4]);
            *reinterpret_cast<float4*>(&As[kr][c4 * 4]) = t;
        }
        // Bs[kk][nn] = W[(a0+nn)*CH + c0+kk]   (c contiguous -> transpose store)
        #pragma unroll
        for (int s = 0; s < 2; s++) {
            int nn = lr + s * 64;
            float4 t = *reinterpret_cast<const float4*>(&W[(size_t)(a0 + nn) * CH + c0 + lq * 4]);
            Bs[lq * 4 + 0][nn] = t.x;
            Bs[lq * 4 + 1][nn] = t.y;
            Bs[lq * 4 + 2][nn] = t.z;
            Bs[lq * 4 + 3][nn] = t.w;
        }
        __syncthreads();
        #pragma unroll
        for (int kk = 0; kk < BKK; kk++) {
            float ra[8], rb[8];
            #pragma unroll
            for (int i = 0; i < 8; i++) ra[i] = As[kk][ty * 8 + i];
            #pragma unroll
            for (int j = 0; j < 8; j++) rb[j] = Bs[kk][tx * 8 + j];
            #pragma unroll
            for (int i = 0; i < 8; i++)
                #pragma unroll
                for (int j = 0; j < 8; j++)
                    acc[i][j] = fmaf(ra[i], rb[j], acc[i][j]);
        }
        __syncthreads();
    }

    float bb[8];
    #pragma unroll
    for (int j = 0; j < 8; j++) bb[j] = bias[a0 + tx * 8 + j];
    #pragma unroll
    for (int i = 0; i < 8; i++) {
        int n = n0 + ty * 8 + i;
        #pragma unroll
        for (int j = 0; j < 8; j += 4) {
            float4 t = make_float4(acc[i][j] + bb[j], acc[i][j + 1] + bb[j + 1],
                                   acc[i][j + 2] + bb[j + 2], acc[i][j + 3] + bb[j + 3]);
            *reinterpret_cast<float4*>(&Y[(size_t)n * AD + a0 + tx * 8 + j]) = t;
        }
    }
}

// ---------------------------------------------------------------------------
// K2: S[n,m] = sum_a q[n,a] * k[m,a]   (NT GEMM, both operands [N,512])
// ---------------------------------------------------------------------------
__global__ __launch_bounds__(256, 2) void k_scores()
{
    int b = blockIdx.z;
    const float* qb = g_q + (size_t)b * HW * AD;
    const float* kb = g_k + (size_t)b * HW * AD;
    float* Sb = g_S + (size_t)b * HW * HW;

    int n0 = blockIdx.y * BM;
    int m0 = blockIdx.x * BN;

    __shared__ float As[BKK][BM + 4];
    __shared__ float Bs[BKK][BN + 4];

    int tid = threadIdx.x;
    int tx = tid & 15, ty = tid >> 4;
    int lr = tid >> 2, lq = tid & 3;

    float acc[8][8];
    #pragma unroll
    for (int i = 0; i < 8; i++)
        #pragma unroll
        for (int j = 0; j < 8; j++) acc[i][j] = 0.f;

    for (int a0 = 0; a0 < AD; a0 += BKK) {
        #pragma unroll
        for (int s = 0; s < 2; s++) {
            int mm = lr + s * 64;
            float4 t = *reinterpret_cast<const float4*>(&qb[(size_t)(n0 + mm) * AD + a0 + lq * 4]);
            As[lq * 4 + 0][mm] = t.x; As[lq * 4 + 1][mm] = t.y;
            As[lq * 4 + 2][mm] = t.z; As[lq * 4 + 3][mm] = t.w;
            float4 u = *reinterpret_cast<const float4*>(&kb[(size_t)(m0 + mm) * AD + a0 + lq * 4]);
            Bs[lq * 4 + 0][mm] = u.x; Bs[lq * 4 + 1][mm] = u.y;
            Bs[lq * 4 + 2][mm] = u.z; Bs[lq * 4 + 3][mm] = u.w;
        }
        __syncthreads();
        #pragma unroll
        for (int kk = 0; kk < BKK; kk++) {
            float ra[8], rb[8];
            #pragma unroll
            for (int i = 0; i < 8; i++) ra[i] = As[kk][ty * 8 + i];
            #pragma unroll
            for (int j = 0; j < 8; j++) rb[j] = Bs[kk][tx * 8 + j];
            #pragma unroll
            for (int i = 0; i < 8; i++)
                #pragma unroll
                for (int j = 0; j < 8; j++)
                    acc[i][j] = fmaf(ra[i], rb[j], acc[i][j]);
        }
        __syncthreads();
    }

    #pragma unroll
    for (int i = 0; i < 8; i++) {
        int n = n0 + ty * 8 + i;
        #pragma unroll
        for (int j = 0; j < 8; j += 4) {
            float4 t = make_float4(acc[i][j], acc[i][j + 1], acc[i][j + 2], acc[i][j + 3]);
            *reinterpret_cast<float4*>(&Sb[(size_t)n * HW + m0 + tx * 8 + j]) = t;
        }
    }
}

// ---------------------------------------------------------------------------
// K3: column softmax (over n, axis=-2) in place: S <- exp(S - colmax)/colsum.
// Block: 256 threads = 64 columns x 4 row-chunks; online softmax + merge.
// ---------------------------------------------------------------------------
__global__ __launch_bounds__(256) void k_softmax()
{
    int b = blockIdx.y;
    int col = threadIdx.x & 63;
    int m = blockIdx.x * 64 + col;
    int rq = threadIdx.x >> 6;          // 0..3
    float* Sb = g_S + (size_t)b * HW * HW;

    int nbeg = rq * (HW / 4), nend = nbeg + (HW / 4);

    float mx = -3.4e38f, den = 0.f;
    for (int n = nbeg; n < nend; n += 8) {
        float v[8];
        #pragma unroll
        for (int u = 0; u < 8; u++) v[u] = Sb[(size_t)(n + u) * HW + m];
        #pragma unroll
        for (int u = 0; u < 8; u++) {
            float val = v[u];
            if (val > mx) { den = den * fast_exp_neg(mx - val) + 1.0f; mx = val; }
            else          { den += fast_exp_neg(val - mx); }
        }
    }

    __shared__ float smx[256], sden[256];
    __shared__ float cmx[64], cinv[64];
    smx[threadIdx.x] = mx; sden[threadIdx.x] = den;
    __syncthreads();
    if (threadIdx.x < 64) {
        float M = smx[threadIdx.x];
        float D = sden[threadIdx.x];
        #pragma unroll
        for (int k = 1; k < 4; k++) {
            float m2 = smx[threadIdx.x + 64 * k];
            float d2 = sden[threadIdx.x + 64 * k];
            float nm = fmaxf(M, m2);
            D = D * fast_exp_neg(M - nm) + d2 * fast_exp_neg(m2 - nm);
            M = nm;
        }
        cmx[threadIdx.x] = M;
        cinv[threadIdx.x] = 1.0f / D;
    }
    __syncthreads();
    float M = cmx[col];
    float inv = cinv[col];

    for (int n = nbeg; n < nend; n += 8) {
        float v[8];
        #pragma unroll
        for (int u = 0; u < 8; u++) v[u] = Sb[(size_t)(n + u) * HW + m];
        #pragma unroll
        for (int u = 0; u < 8; u++) v[u] = fast_exp_neg(v[u] - M) * inv;
        #pragma unroll
        for (int u = 0; u < 8; u++) Sb[(size_t)(n + u) * HW + m] = v[u];
    }
}

// ---------------------------------------------------------------------------
// K4: out[n,c] = sum_m P[n,m] * v[m,c]; result = x_flat + 0.1*out_flat
// (the reference .view() is a raw reinterpret -> flat elementwise residual)
// ---------------------------------------------------------------------------
__global__ __launch_bounds__(256, 2) void k_out(
    const float* __restrict__ x, float* __restrict__ out)
{
    int b = blockIdx.z;
    const float* Pb = g_S + (size_t)b * HW * HW;
    const float* vb = g_v + (size_t)b * HW * CH;

    int c0 = blockIdx.x * BN;
    int n0 = blockIdx.y * BM;

    __shared__ float As[BKK][BM + 4];
    __shared__ float Bs[BKK][BN + 4];

    int tid = threadIdx.x;
    int tx = tid & 15, ty = tid >> 4;
    int r8 = tid >> 5, c4 = tid & 31;
    int lr = tid >> 2, lq = tid & 3;

    float acc[8][8];
    #pragma unroll
    for (int i = 0; i < 8; i++)
        #pragma unroll
        for (int j = 0; j < 8; j++) acc[i][j] = 0.f;

    for (int m0 = 0; m0 < HW; m0 += BKK) {
        // As[kk][mm] = P[(n0+mm)*HW + m0+kk]  (m contiguous -> transpose store)
        #pragma unroll
        for (int s = 0; s < 2; s++) {
            int mm = lr + s * 64;
            float4 t = *reinterpret_cast<const float4*>(&Pb[(size_t)(n0 + mm) * HW + m0 + lq * 4]);
            As[lq * 4 + 0][mm] = t.x; As[lq * 4 + 1][mm] = t.y;
            As[lq * 4 + 2][mm] = t.z; As[lq * 4 + 3][mm] = t.w;
        }
        // Bs[kk][nn] = v[(m0+kk)*CH + c0+nn]  (c contiguous -> direct float4)
        #pragma unroll
        for (int s = 0; s < 2; s++) {
            int kr = r8 + s * 8;
            float4 t = *reinterpret_cast<const float4*>(&vb[(size_t)(m0 + kr) * CH + c0 + c4 * 4]);
            *reinterpret_cast<float4*>(&Bs[kr][c4 * 4]) = t;
        }
        __syncthreads();
        #pragma unroll
        for (int kk = 0; kk < BKK; kk++) {
            float ra[8], rb[8];
            #pragma unroll
            for (int i = 0; i < 8; i++) ra[i] = As[kk][ty * 8 + i];
            #pragma unroll
            for (int j = 0; j < 8; j++) rb[j] = Bs[kk][tx * 8 + j];
            #pragma unroll
            for (int i = 0; i < 8; i++)
                #pragma unroll
                for (int j = 0; j < 8; j++)
                    acc[i][j] = fmaf(ra[i], rb[j], acc[i][j]);
        }
        __syncthreads();
    }

    const float* xb = x + (size_t)b * CH * HW;
    float* ob = out + (size_t)b * CH * HW;
    #pragma unroll
    for (int i = 0; i < 8; i++) {
        int n = n0 + ty * 8 + i;
        #pragma unroll
        for (int j = 0; j < 8; j += 4) {
            size_t off = (size_t)n * CH + c0 + tx * 8 + j;
            float4 xv = *reinterpret_cast<const float4*>(&xb[off]);
            float4 t = make_float4(fmaf(0.1f, acc[i][j],     xv.x),
                                   fmaf(0.1f, acc[i][j + 1], xv.y),
                                   fmaf(0.1f, acc[i][j + 2], xv.z),
                                   fmaf(0.1f, acc[i][j + 3], xv.w));
            *reinterpret_cast<float4*>(&ob[off]) = t;
        }
    }
}

// ---------------------------------------------------------------------------
extern "C" void kernel_launch(void* const* d_in, const int* in_sizes, int n_in,
                              void* d_out, int out_size)
{
    const float* x  = (const float*)d_in[0];
    const float* Wq = (const float*)d_in[1];
    const float* bq = (const float*)d_in[2];
    const float* Wk = (const float*)d_in[3];
    const float* bk = (const float*)d_in[4];
    const float* Wv = (const float*)d_in[5];
    const float* bv = (const float*)d_in[6];
    float* out = (float*)d_out;

    k_proj   <<<dim3(HW / BM, AD / BN, BATCH * 3), 256>>>(x, Wq, bq, Wk, bk, Wv, bv);
    k_scores <<<dim3(HW / BN, HW / BM, BATCH), 256>>>();
    k_softmax<<<dim3(HW / 64, BATCH), 256>>>();
    k_out    <<<dim3(CH / BN, HW / BM, BATCH), 256>>>(x, out);
}

// round 3
// speedup vs baseline: 1.6126x; 1.6126x over previous
#include <cuda_runtime.h>
#include <cuda_bf16.h>
#include <cstdint>

#define BATCH 4
#define CH    512
#define HW    4096
#define AD    512

typedef __nv_bfloat16 bf16;

// ---------------- scratch (__device__ globals; no allocation) ---------------
__device__ bf16 g_qh[BATCH * HW * AD];
__device__ bf16 g_ql[BATCH * HW * AD];
__device__ bf16 g_kh[BATCH * HW * AD];
__device__ bf16 g_kl[BATCH * HW * AD];
__device__ bf16 g_vth[BATCH * CH * HW];   // v transposed: [b][c][n]
__device__ bf16 g_vtl[BATCH * CH * HW];
__device__ float g_S[(size_t)BATCH * HW * HW];   // scores fp32
__device__ bf16 g_ph[(size_t)BATCH * HW * HW];   // softmax probs hi/lo
__device__ bf16 g_pl[(size_t)BATCH * HW * HW];

// ---------------- helpers ----------------------------------------------------
__device__ __forceinline__ uint32_t smem_u32(const void* p) {
    uint32_t a;
    asm("{ .reg .u64 t; cvta.to.shared.u64 t, %1; cvt.u32.u64 %0, t; }" : "=r"(a) : "l"(p));
    return a;
}
__device__ __forceinline__ void cp16(uint32_t d, const void* s) {
    asm volatile("cp.async.ca.shared.global [%0], [%1], 16;" :: "r"(d), "l"(s));
}
__device__ __forceinline__ void cp_commit() { asm volatile("cp.async.commit_group;" ::: "memory"); }
__device__ __forceinline__ void cp_wait0()  { asm volatile("cp.async.wait_group 0;" ::: "memory"); }

__device__ __forceinline__ uint32_t lds32(const bf16* base, int halfoff) {
    return *reinterpret_cast<const uint32_t*>(base + halfoff);
}

__device__ __forceinline__ void mma16816(float* c,
    uint32_t a0, uint32_t a1, uint32_t a2, uint32_t a3, uint32_t b0, uint32_t b1)
{
    asm volatile(
        "mma.sync.aligned.m16n8k16.row.col.f32.bf16.bf16.f32 "
        "{%0,%1,%2,%3},{%4,%5,%6,%7},{%8,%9},{%0,%1,%2,%3};"
        : "+f"(c[0]), "+f"(c[1]), "+f"(c[2]), "+f"(c[3])
        : "r"(a0), "r"(a1), "r"(a2), "r"(a3), "r"(b0), "r"(b1));
}

// FMA-only exp (x <= 0)
__device__ __forceinline__ float fast_exp_neg(float x) {
    float t = x * 1.4426950408889634f;
    t = fmaxf(t, -126.0f);
    float r = rintf(t);
    float f = t - r;
    float p = 1.3333558e-3f;
    p = fmaf(p, f, 9.6181291e-3f);
    p = fmaf(p, f, 5.5504110e-2f);
    p = fmaf(p, f, 2.4022651e-1f);
    p = fmaf(p, f, 6.9314718e-1f);
    p = fmaf(p, f, 1.0f);
    return __int_as_float(__float_as_int(p) + ((int)r << 23));
}

// ---------------- smem layout for mma kernels -------------------------------
// 4 tiles (Ah, Al, Bh, Bl), each 128 rows x 16 halves, row stride 24 halves
// (48B: conflict-free for both A-frag and B-frag lane patterns), double-buffered.
#define TT      24          // row stride (halves)
#define TILE_H  3072        // halves per tile (128*24)
#define TILE_B  6144
#define STAGE_H 12288
#define STAGE_B 24576
#define SMEM_GEMM (2 * STAGE_B)   // 49152

__device__ __forceinline__ void stage_load(uint32_t sb, int st,
    const bf16* __restrict__ Ah, const bf16* __restrict__ Al,
    const bf16* __restrict__ Bh, const bf16* __restrict__ Bl,
    int ldA, int ldB, int k0, int tid)
{
    int row = tid >> 1;
    int ho  = (tid & 1) * 8;
    uint32_t dbase = sb + st * STAGE_B + row * 48 + (tid & 1) * 16;
    cp16(dbase + 0 * TILE_B, Ah + (size_t)row * ldA + k0 + ho);
    cp16(dbase + 1 * TILE_B, Al + (size_t)row * ldA + k0 + ho);
    cp16(dbase + 2 * TILE_B, Bh + (size_t)row * ldB + k0 + ho);
    cp16(dbase + 3 * TILE_B, Bl + (size_t)row * ldB + k0 + ho);
    cp_commit();
}

__device__ __forceinline__ void stage_mma(const bf16* smst, float acc[4][4][4],
                                          int wm, int wn, int g, int tg)
{
    const bf16* sAh = smst;
    const bf16* sAl = smst + TILE_H;
    const bf16* sBh = smst + 2 * TILE_H;
    const bf16* sBl = smst + 3 * TILE_H;

    uint32_t ah[4][4], bh[4][2];
    #pragma unroll
    for (int i = 0; i < 4; i++) {
        int r = wm * 64 + i * 16 + g;
        ah[i][0] = lds32(sAh, r * TT + tg * 2);
        ah[i][1] = lds32(sAh, (r + 8) * TT + tg * 2);
        ah[i][2] = lds32(sAh, r * TT + tg * 2 + 8);
        ah[i][3] = lds32(sAh, (r + 8) * TT + tg * 2 + 8);
    }
    #pragma unroll
    for (int j = 0; j < 4; j++) {
        int r = wn * 32 + j * 8 + g;
        bh[j][0] = lds32(sBh, r * TT + tg * 2);
        bh[j][1] = lds32(sBh, r * TT + tg * 2 + 8);
    }
    #pragma unroll
    for (int i = 0; i < 4; i++)
        #pragma unroll
        for (int j = 0; j < 4; j++)
            mma16816(acc[i][j], ah[i][0], ah[i][1], ah[i][2], ah[i][3], bh[j][0], bh[j][1]);

    uint32_t bl[4][2];
    #pragma unroll
    for (int j = 0; j < 4; j++) {
        int r = wn * 32 + j * 8 + g;
        bl[j][0] = lds32(sBl, r * TT + tg * 2);
        bl[j][1] = lds32(sBl, r * TT + tg * 2 + 8);
    }
    #pragma unroll
    for (int i = 0; i < 4; i++)
        #pragma unroll
        for (int j = 0; j < 4; j++)
            mma16816(acc[i][j], ah[i][0], ah[i][1], ah[i][2], ah[i][3], bl[j][0], bl[j][1]);

    uint32_t al[4][4];
    #pragma unroll
    for (int i = 0; i < 4; i++) {
        int r = wm * 64 + i * 16 + g;
        al[i][0] = lds32(sAl, r * TT + tg * 2);
        al[i][1] = lds32(sAl, (r + 8) * TT + tg * 2);
        al[i][2] = lds32(sAl, r * TT + tg * 2 + 8);
        al[i][3] = lds32(sAl, (r + 8) * TT + tg * 2 + 8);
    }
    #pragma unroll
    for (int i = 0; i < 4; i++)
        #pragma unroll
        for (int j = 0; j < 4; j++)
            mma16816(acc[i][j], al[i][0], al[i][1], al[i][2], al[i][3], bh[j][0], bh[j][1]);
}

// ---------------------------------------------------------------------------
// K1: fused projections (fp32 CUDA-core GEMM), emits bf16 hi/lo splits.
// ---------------------------------------------------------------------------
#define BM 128
#define BN 128
#define BKK 16

__global__ __launch_bounds__(256, 2) void k_proj(
    const float* __restrict__ x,
    const float* __restrict__ Wq, const float* __restrict__ bq,
    const float* __restrict__ Wk, const float* __restrict__ bk,
    const float* __restrict__ Wv, const float* __restrict__ bv)
{
    int z = blockIdx.z;
    int b = z / 3, p = z % 3;
    const float* W    = (p == 0) ? Wq : ((p == 1) ? Wk : Wv);
    const float* bias = (p == 0) ? bq : ((p == 1) ? bk : bv);
    const float* X = x + (size_t)b * CH * HW;

    int n0 = blockIdx.x * BM;
    int a0 = blockIdx.y * BN;

    __shared__ float As[BKK][BM + 4];
    __shared__ float Bs[BKK][BN + 4];

    int tid = threadIdx.x;
    int tx = tid & 15, ty = tid >> 4;
    int r8 = tid >> 5, c4 = tid & 31;
    int lr = tid >> 2, lq = tid & 3;

    float acc[8][8];
    #pragma unroll
    for (int i = 0; i < 8; i++)
        #pragma unroll
        for (int j = 0; j < 8; j++) acc[i][j] = 0.f;

    for (int c0 = 0; c0 < CH; c0 += BKK) {
        #pragma unroll
        for (int s = 0; s < 2; s++) {
            int kr = r8 + s * 8;
            float4 t = *reinterpret_cast<const float4*>(&X[(size_t)(c0 + kr) * HW + n0 + c4 * 4]);
            *reinterpret_cast<float4*>(&As[kr][c4 * 4]) = t;
        }
        #pragma unroll
        for (int s = 0; s < 2; s++) {
            int nn = lr + s * 64;
            float4 t = *reinterpret_cast<const float4*>(&W[(size_t)(a0 + nn) * CH + c0 + lq * 4]);
            Bs[lq * 4 + 0][nn] = t.x; Bs[lq * 4 + 1][nn] = t.y;
            Bs[lq * 4 + 2][nn] = t.z; Bs[lq * 4 + 3][nn] = t.w;
        }
        __syncthreads();
        #pragma unroll
        for (int kk = 0; kk < BKK; kk++) {
            float ra[8], rb[8];
            #pragma unroll
            for (int i = 0; i < 8; i++) ra[i] = As[kk][ty * 8 + i];
            #pragma unroll
            for (int j = 0; j < 8; j++) rb[j] = Bs[kk][tx * 8 + j];
            #pragma unroll
            for (int i = 0; i < 8; i++)
                #pragma unroll
                for (int j = 0; j < 8; j++)
                    acc[i][j] = fmaf(ra[i], rb[j], acc[i][j]);
        }
        __syncthreads();
    }

    float bb[8];
    #pragma unroll
    for (int j = 0; j < 8; j++) bb[j] = bias[a0 + tx * 8 + j];

    if (p < 2) {
        bf16* Yh = ((p == 0) ? g_qh : g_kh) + (size_t)b * HW * AD;
        bf16* Yl = ((p == 0) ? g_ql : g_kl) + (size_t)b * HW * AD;
        #pragma unroll
        for (int i = 0; i < 8; i++) {
            int n = n0 + ty * 8 + i;
            __align__(16) bf16 h8[8], l8[8];
            #pragma unroll
            for (int j = 0; j < 8; j++) {
                float val = acc[i][j] + bb[j];
                bf16 h = __float2bfloat16(val);
                h8[j] = h;
                l8[j] = __float2bfloat16(val - __bfloat162float(h));
            }
            size_t off = (size_t)n * AD + a0 + tx * 8;
            *reinterpret_cast<float4*>(&Yh[off]) = *reinterpret_cast<const float4*>(h8);
            *reinterpret_cast<float4*>(&Yl[off]) = *reinterpret_cast<const float4*>(l8);
        }
    } else {
        bf16* Th = g_vth + (size_t)b * CH * HW;
        bf16* Tl = g_vtl + (size_t)b * CH * HW;
        #pragma unroll
        for (int j = 0; j < 8; j++) {
            int c = a0 + tx * 8 + j;
            __align__(16) bf16 h8[8], l8[8];
            #pragma unroll
            for (int i = 0; i < 8; i++) {
                float val = acc[i][j] + bb[j];
                bf16 h = __float2bfloat16(val);
                h8[i] = h;
                l8[i] = __float2bfloat16(val - __bfloat162float(h));
            }
            size_t off = (size_t)c * HW + n0 + ty * 8;
            *reinterpret_cast<float4*>(&Th[off]) = *reinterpret_cast<const float4*>(h8);
            *reinterpret_cast<float4*>(&Tl[off]) = *reinterpret_cast<const float4*>(l8);
        }
    }
}

// ---------------------------------------------------------------------------
// K2: S = Q K^T via mma.sync bf16 splits (3 products). Tile 128x128, kc=16.
// ---------------------------------------------------------------------------
__global__ __launch_bounds__(256) void k_scores_mma()
{
    extern __shared__ bf16 sm[];
    uint32_t sb = smem_u32(sm);
    int tid = threadIdx.x, lane = tid & 31, wid = tid >> 5;
    int wm = wid & 1, wn = wid >> 1, g = lane >> 2, tg = lane & 3;

    int b = blockIdx.z;
    int m0 = blockIdx.x * 128;   // key block (cols)
    int n0 = blockIdx.y * 128;   // query block (rows)

    const bf16* Ah = g_qh + ((size_t)b * HW + n0) * AD;
    const bf16* Al = g_ql + ((size_t)b * HW + n0) * AD;
    const bf16* Bh = g_kh + ((size_t)b * HW + m0) * AD;
    const bf16* Bl = g_kl + ((size_t)b * HW + m0) * AD;

    float acc[4][4][4];
    #pragma unroll
    for (int i = 0; i < 4; i++)
        #pragma unroll
        for (int j = 0; j < 4; j++)
            #pragma unroll
            for (int r = 0; r < 4; r++) acc[i][j][r] = 0.f;

    stage_load(sb, 0, Ah, Al, Bh, Bl, AD, AD, 0, tid);
    const int KS = AD / 16;
    for (int s = 0; s < KS; s++) {
        cp_wait0();
        __syncthreads();
        if (s + 1 < KS)
            stage_load(sb, (s + 1) & 1, Ah, Al, Bh, Bl, AD, AD, (s + 1) * 16, tid);
        stage_mma(sm + (s & 1) * STAGE_H, acc, wm, wn, g, tg);
        __syncthreads();
    }

    float* Sb = g_S + (size_t)b * HW * HW;
    #pragma unroll
    for (int i = 0; i < 4; i++) {
        int n = n0 + wm * 64 + i * 16 + g;
        #pragma unroll
        for (int j = 0; j < 4; j++) {
            int m = m0 + wn * 32 + j * 8 + tg * 2;
            *reinterpret_cast<float2*>(&Sb[(size_t)n * HW + m]) =
                make_float2(acc[i][j][0], acc[i][j][1]);
            *reinterpret_cast<float2*>(&Sb[(size_t)(n + 8) * HW + m]) =
                make_float2(acc[i][j][2], acc[i][j][3]);
        }
    }
}

// ---------------------------------------------------------------------------
// K3: column softmax (axis=-2); reads S fp32, writes P hi/lo bf16 splits.
// ---------------------------------------------------------------------------
__global__ __launch_bounds__(256) void k_softmax()
{
    int b = blockIdx.y;
    int col = threadIdx.x & 63;
    int m = blockIdx.x * 64 + col;
    int rq = threadIdx.x >> 6;
    const float* Sb = g_S + (size_t)b * HW * HW;
    bf16* Ph = g_ph + (size_t)b * HW * HW;
    bf16* Pl = g_pl + (size_t)b * HW * HW;

    int nbeg = rq * (HW / 4), nend = nbeg + (HW / 4);

    float mx = -3.4e38f, den = 0.f;
    for (int n = nbeg; n < nend; n += 8) {
        float v[8];
        #pragma unroll
        for (int u = 0; u < 8; u++) v[u] = Sb[(size_t)(n + u) * HW + m];
        #pragma unroll
        for (int u = 0; u < 8; u++) {
            float val = v[u];
            if (val > mx) { den = den * fast_exp_neg(mx - val) + 1.0f; mx = val; }
            else          { den += fast_exp_neg(val - mx); }
        }
    }

    __shared__ float smx[256], sden[256];
    __shared__ float cmx[64], cinv[64];
    smx[threadIdx.x] = mx; sden[threadIdx.x] = den;
    __syncthreads();
    if (threadIdx.x < 64) {
        float M = smx[threadIdx.x], D = sden[threadIdx.x];
        #pragma unroll
        for (int k = 1; k < 4; k++) {
            float m2 = smx[threadIdx.x + 64 * k], d2 = sden[threadIdx.x + 64 * k];
            float nm = fmaxf(M, m2);
            D = D * fast_exp_neg(M - nm) + d2 * fast_exp_neg(m2 - nm);
            M = nm;
        }
        cmx[threadIdx.x] = M;
        cinv[threadIdx.x] = 1.0f / D;
    }
    __syncthreads();
    float M = cmx[col], inv = cinv[col];

    for (int n = nbeg; n < nend; n += 8) {
        float v[8];
        #pragma unroll
        for (int u = 0; u < 8; u++) v[u] = Sb[(size_t)(n + u) * HW + m];
        #pragma unroll
        for (int u = 0; u < 8; u++) {
            float pv = fast_exp_neg(v[u] - M) * inv;
            bf16 h = __float2bfloat16(pv);
            Ph[(size_t)(n + u) * HW + m] = h;
            Pl[(size_t)(n + u) * HW + m] = __float2bfloat16(pv - __bfloat162float(h));
        }
    }
}

// ---------------------------------------------------------------------------
// K4: O = P V via mma.sync bf16 splits + residual. Tile 128(n) x 128(c), K=4096.
// ---------------------------------------------------------------------------
__global__ __launch_bounds__(256) void k_out_mma(
    const float* __restrict__ x, float* __restrict__ out)
{
    extern __shared__ bf16 sm[];
    uint32_t sb = smem_u32(sm);
    int tid = threadIdx.x, lane = tid & 31, wid = tid >> 5;
    int wm = wid & 1, wn = wid >> 1, g = lane >> 2, tg = lane & 3;

    int b = blockIdx.z;
    int c0 = blockIdx.x * 128;   // channel block (cols)
    int n0 = blockIdx.y * 128;   // row block

    const bf16* Ah = g_ph + (size_t)b * HW * HW + (size_t)n0 * HW;
    const bf16* Al = g_pl + (size_t)b * HW * HW + (size_t)n0 * HW;
    const bf16* Bh = g_vth + ((size_t)b * CH + c0) * HW;
    const bf16* Bl = g_vtl + ((size_t)b * CH + c0) * HW;

    float acc[4][4][4];
    #pragma unroll
    for (int i = 0; i < 4; i++)
        #pragma unroll
        for (int j = 0; j < 4; j++)
            #pragma unroll
            for (int r = 0; r < 4; r++) acc[i][j][r] = 0.f;

    stage_load(sb, 0, Ah, Al, Bh, Bl, HW, HW, 0, tid);
    const int KS = HW / 16;
    for (int s = 0; s < KS; s++) {
        cp_wait0();
        __syncthreads();
        if (s + 1 < KS)
            stage_load(sb, (s + 1) & 1, Ah, Al, Bh, Bl, HW, HW, (s + 1) * 16, tid);
        stage_mma(sm + (s & 1) * STAGE_H, acc, wm, wn, g, tg);
        __syncthreads();
    }

    const float* xb = x + (size_t)b * CH * HW;
    float* ob = out + (size_t)b * CH * HW;
    #pragma unroll
    for (int i = 0; i < 4; i++) {
        int n = n0 + wm * 64 + i * 16 + g;
        #pragma unroll
        for (int j = 0; j < 4; j++) {
            int c = c0 + wn * 32 + j * 8 + tg * 2;
            {
                size_t off = (size_t)n * CH + c;
                float2 xv = *reinterpret_cast<const float2*>(&xb[off]);
                *reinterpret_cast<float2*>(&ob[off]) =
                    make_float2(fmaf(0.1f, acc[i][j][0], xv.x),
                                fmaf(0.1f, acc[i][j][1], xv.y));
            }
            {
                size_t off = (size_t)(n + 8) * CH + c;
                float2 xv = *reinterpret_cast<const float2*>(&xb[off]);
                *reinterpret_cast<float2*>(&ob[off]) =
                    make_float2(fmaf(0.1f, acc[i][j][2], xv.x),
                                fmaf(0.1f, acc[i][j][3], xv.y));
            }
        }
    }
}

// ---------------------------------------------------------------------------
extern "C" void kernel_launch(void* const* d_in, const int* in_sizes, int n_in,
                              void* d_out, int out_size)
{
    const float* x  = (const float*)d_in[0];
    const float* Wq = (const float*)d_in[1];
    const float* bq = (const float*)d_in[2];
    const float* Wk = (const float*)d_in[3];
    const float* bk = (const float*)d_in[4];
    const float* Wv = (const float*)d_in[5];
    const float* bv = (const float*)d_in[6];
    float* out = (float*)d_out;

    static int configured = 0;
    if (!configured) {
        cudaFuncSetAttribute(k_scores_mma, cudaFuncAttributeMaxDynamicSharedMemorySize, SMEM_GEMM);
        cudaFuncSetAttribute(k_out_mma,    cudaFuncAttributeMaxDynamicSharedMemorySize, SMEM_GEMM);
        configured = 1;
    }

    k_proj      <<<dim3(HW / BM, AD / BN, BATCH * 3), 256>>>(x, Wq, bq, Wk, bk, Wv, bv);
    k_scores_mma<<<dim3(HW / 128, HW / 128, BATCH), 256, SMEM_GEMM>>>();
    k_softmax   <<<dim3(HW / 64, BATCH), 256>>>();
    k_out_mma   <<<dim3(CH / 128, HW / 128, BATCH), 256, SMEM_GEMM>>>(x, out);
}